// round 4
// baseline (speedup 1.0000x reference)
#include <cuda_runtime.h>
#include <math.h>
#include <stddef.h>
#include <stdint.h>

#define B_ 256
#define W_ 512
#define F_ 512
#define N_ 512
#define WT 16   // words per tile in fused attention pass (== #warps)

// Scratch (device globals — no allocation allowed)
__device__ float g_t [B_*F_];   // t  = sum_w w[w]*x[b,w,:]
__device__ float g_q [B_*N_];   // Q  = t @ wq
__device__ float g_qk[B_*F_];   // qk = (Q @ wk^T) * rsqrt(N)
__device__ float g_y [B_*F_];   // y  = sum_w softmax_w * x[b,w,:]

// ---------------------------------------------------------------------------
// cp.async helpers
// ---------------------------------------------------------------------------
__device__ __forceinline__ void cp_async16(void* dst_smem, const void* src_gmem) {
    uint32_t d = (uint32_t)__cvta_generic_to_shared(dst_smem);
    asm volatile("cp.async.cg.shared.global [%0], [%1], 16;\n" :: "r"(d), "l"(src_gmem));
}
__device__ __forceinline__ void cp_commit() {
    asm volatile("cp.async.commit_group;\n");
}
template <int Nw>
__device__ __forceinline__ void cp_wait() {
    asm volatile("cp.async.wait_group %0;\n" :: "n"(Nw));
}

// ---------------------------------------------------------------------------
// K1: t[b][f] = sum_w w[w] * x[b][w][f]   (streaming pass 1 over x)
// 2 batches per CTA -> grid 128 = one balanced wave. float4 loads.
// Thread owns float4 column c4 = tid&127, w-quarter q = tid>>7.
// ---------------------------------------------------------------------------
__global__ __launch_bounds__(512) void k_t(const float* __restrict__ x,
                                           const float* __restrict__ wvec) {
    __shared__ float ws[W_];
    __shared__ float4 red[2][4][128];   // 16 KB
    const int tid = threadIdx.x;
    const int q = tid >> 7, c4 = tid & 127;
    ws[tid] = wvec[tid];
    __syncthreads();

    const int b0 = blockIdx.x * 2;
    const float4* x0 = (const float4*)(x + (size_t)b0 * W_ * F_) + c4;
    const float4* x1 = (const float4*)(x + (size_t)(b0 + 1) * W_ * F_) + c4;

    float4 a0 = {0.f, 0.f, 0.f, 0.f};
    float4 a1 = {0.f, 0.f, 0.f, 0.f};
    const int wbase = q * 128;
    #pragma unroll 4
    for (int i = 0; i < 128; i++) {
        const int w = wbase + i;
        const float wv = ws[w];
        const float4 v0 = x0[(size_t)w * 128];
        const float4 v1 = x1[(size_t)w * 128];
        a0.x += wv * v0.x; a0.y += wv * v0.y; a0.z += wv * v0.z; a0.w += wv * v0.w;
        a1.x += wv * v1.x; a1.y += wv * v1.y; a1.z += wv * v1.z; a1.w += wv * v1.w;
    }
    red[0][q][c4] = a0;
    red[1][q][c4] = a1;
    __syncthreads();

    if (tid < 256) {
        const int bs = tid >> 7, c = tid & 127;
        float4 r0 = red[bs][0][c], r1 = red[bs][1][c];
        float4 r2 = red[bs][2][c], r3 = red[bs][3][c];
        float4 o;
        o.x = (r0.x + r1.x) + (r2.x + r3.x);
        o.y = (r0.y + r1.y) + (r2.y + r3.y);
        o.z = (r0.z + r1.z) + (r2.z + r3.z);
        o.w = (r0.w + r1.w) + (r2.w + r3.w);
        ((float4*)(g_t + (size_t)(b0 + bs) * F_))[c] = o;
    }
}

// ---------------------------------------------------------------------------
// Tiled 64x64 SGEMM.  C[M,Nn] = A[M,Kk] @ (TRANS_B ? Bm[Nn,Kk]^T : Bm[Kk,Nn]) * scale
// ---------------------------------------------------------------------------
template <int TRANS_B>
__global__ __launch_bounds__(256) void gemm64(const float* __restrict__ A,
                                              const float* __restrict__ Bm,
                                              float* __restrict__ C,
                                              int M, int Nn, int Kk, float scale) {
    __shared__ float As[16][65];
    __shared__ float Bs[16][65];
    const int tid = threadIdx.x;
    const int tx = tid & 15, ty = tid >> 4;
    const int m0 = blockIdx.y * 64, n0 = blockIdx.x * 64;
    float c[4][4] = {};

    for (int k0 = 0; k0 < Kk; k0 += 16) {
        #pragma unroll
        for (int j = 0; j < 4; j++) {
            int e = tid * 4 + j;
            int m = e >> 4, k = e & 15;
            As[k][m] = A[(size_t)(m0 + m) * Kk + k0 + k];
        }
        #pragma unroll
        for (int j = 0; j < 4; j++) {
            int e = tid * 4 + j;
            if (TRANS_B) {
                int n = e >> 4, k = e & 15;
                Bs[k][n] = Bm[(size_t)(n0 + n) * Kk + k0 + k];
            } else {
                int k = e >> 6, n = e & 63;
                Bs[k][n] = Bm[(size_t)(k0 + k) * Nn + n0 + n];
            }
        }
        __syncthreads();
        #pragma unroll
        for (int k = 0; k < 16; k++) {
            float a[4], bb[4];
            #pragma unroll
            for (int i = 0; i < 4; i++) a[i]  = As[k][ty * 4 + i];
            #pragma unroll
            for (int j = 0; j < 4; j++) bb[j] = Bs[k][tx * 4 + j];
            #pragma unroll
            for (int i = 0; i < 4; i++)
                #pragma unroll
                for (int j = 0; j < 4; j++) c[i][j] += a[i] * bb[j];
        }
        __syncthreads();
    }
    #pragma unroll
    for (int i = 0; i < 4; i++)
        #pragma unroll
        for (int j = 0; j < 4; j++)
            C[(size_t)(m0 + ty * 4 + i) * Nn + n0 + tx * 4 + j] = c[i][j] * scale;
}

// ---------------------------------------------------------------------------
// K3: fused scores + online softmax + weighted-x accumulate (pass 2 over x).
// One CTA per batch. cp.async double-buffered WT x F_ tiles, 2 CTAs/SM.
// Dynamic smem layout: qks[512] | buf0[WT*512] | buf1[WT*512]  (67584 B)
// ---------------------------------------------------------------------------
__global__ __launch_bounds__(512, 2) void k_attn(const float* __restrict__ x) {
    extern __shared__ float sm[];
    float* qks = sm;                         // 512
    float* bufs[2] = { sm + F_, sm + F_ + WT * F_ };
    __shared__ float sc[WT];

    const int b = blockIdx.x, tid = threadIdx.x;
    const int wi = tid >> 5, lane = tid & 31;

    qks[tid] = g_qk[b * F_ + tid];
    const float4* xb = (const float4*)(x + (size_t)b * W_ * F_);

    // Preload tile 0
    #pragma unroll
    for (int j = 0; j < 4; j++) {
        int e = tid + j * 512;               // 0..2047
        int w = e >> 7, f4 = e & 127;
        cp_async16(&bufs[0][w * F_ + f4 * 4], &xb[(size_t)w * 128 + f4]);
    }
    cp_commit();
    __syncthreads();                         // qks visible

    float qkr[16];
    #pragma unroll
    for (int j = 0; j < 16; j++) qkr[j] = qks[lane + 32 * j];

    float m = -1e30f, s = 0.f, y = 0.f;

    for (int t = 0; t < W_ / WT; t++) {
        const int cur = t & 1, nxt = cur ^ 1;
        if (t < W_ / WT - 1) {
            const int t0 = (t + 1) * WT;
            #pragma unroll
            for (int j = 0; j < 4; j++) {
                int e = tid + j * 512;
                int w = e >> 7, f4 = e & 127;
                cp_async16(&bufs[nxt][w * F_ + f4 * 4], &xb[(size_t)(t0 + w) * 128 + f4]);
            }
            cp_commit();
            cp_wait<1>();                    // current tile's group done
        } else {
            cp_wait<0>();
        }
        __syncthreads();

        // Each warp computes one word's dot product (qk already scaled)
        float d = 0.f;
        const float* xw = &bufs[cur][wi * F_];
        #pragma unroll
        for (int j = 0; j < 16; j++) d += xw[lane + 32 * j] * qkr[j];
        #pragma unroll
        for (int o = 16; o > 0; o >>= 1) d += __shfl_xor_sync(0xffffffffu, d, o);
        if (lane == 0) sc[wi] = d;
        __syncthreads();

        // Online softmax update (thread owns f = tid)
        float mn = m;
        #pragma unroll
        for (int w = 0; w < WT; w++) mn = fmaxf(mn, sc[w]);
        const float corr = __expf(m - mn);
        s *= corr;
        y *= corr;
        #pragma unroll
        for (int w = 0; w < WT; w++) {
            float p = __expf(sc[w] - mn);
            s += p;
            y += p * bufs[cur][w * F_ + tid];
        }
        m = mn;
        __syncthreads();                     // protect sc + buf[nxt] reuse
    }
    g_y[b * F_ + tid] = y / s;
}

// ---------------------------------------------------------------------------
extern "C" void kernel_launch(void* const* d_in, const int* in_sizes, int n_in,
                              void* d_out, int out_size) {
    const float* x    = (const float*)d_in[0];
    const float* wk   = (const float*)d_in[1];
    const float* wq   = (const float*)d_in[2];
    const float* wv   = (const float*)d_in[3];
    const float* wvec = (const float*)d_in[4];
    float* out = (float*)d_out;

    float *pt, *pq, *pqk, *py;
    cudaGetSymbolAddress((void**)&pt,  g_t);
    cudaGetSymbolAddress((void**)&pq,  g_q);
    cudaGetSymbolAddress((void**)&pqk, g_qk);
    cudaGetSymbolAddress((void**)&py,  g_y);

    const int attn_smem = (F_ + 2 * WT * F_) * sizeof(float);   // 67584
    cudaFuncSetAttribute(k_attn, cudaFuncAttributeMaxDynamicSharedMemorySize, attn_smem);

    const float rsqrtN = 0.04419417382415922f;  // 1/sqrt(512)

    // Pass 1 over x: t   (2 batches per CTA)
    k_t<<<B_ / 2, 512>>>(x, wvec);
    // Q = t @ wq
    gemm64<0><<<dim3(N_ / 64, B_ / 64), 256>>>(pt, wq, pq, B_, N_, F_, 1.f);
    // qk = (Q @ wk^T) * rsqrt(N)
    gemm64<1><<<dim3(F_ / 64, B_ / 64), 256>>>(pq, wk, pqk, B_, F_, N_, rsqrtN);
    // Pass 2 over x: fused scores + softmax + y
    k_attn<<<B_, 512, attn_smem>>>(x);
    // out = y @ wv
    gemm64<0><<<dim3(N_ / 64, B_ / 64), 256>>>(py, wv, out, B_, N_, F_, 1.f);
}

// round 5
// speedup vs baseline: 1.4674x; 1.4674x over previous
#include <cuda_runtime.h>
#include <math.h>
#include <stddef.h>
#include <stdint.h>

#define B_ 256
#define W_ 512
#define F_ 512
#define N_ 512
#define WT 16   // words per tile in fused attention pass (== #warps)

// Scratch (device globals — no allocation allowed)
__device__ float g_Mqk[F_*F_];  // (wq @ wk^T) * rsqrt(N)   — weights only, 1 MB
__device__ float g_y  [B_*F_];  // y = sum_w softmax_w * x[b,w,:]

// ---------------------------------------------------------------------------
// cp.async helpers
// ---------------------------------------------------------------------------
__device__ __forceinline__ void cp_async16(void* dst_smem, const void* src_gmem) {
    uint32_t d = (uint32_t)__cvta_generic_to_shared(dst_smem);
    asm volatile("cp.async.cg.shared.global [%0], [%1], 16;\n" :: "r"(d), "l"(src_gmem));
}
__device__ __forceinline__ void cp_commit() {
    asm volatile("cp.async.commit_group;\n");
}
template <int Nw>
__device__ __forceinline__ void cp_wait() {
    asm volatile("cp.async.wait_group %0;\n" :: "n"(Nw));
}

// ---------------------------------------------------------------------------
// 32x32 tiled SGEMM, BK=32.  C = A[M,Kk] @ (TRANS_B ? Bm[Nn,Kk]^T : Bm[Kk,Nn]) * scale
// 256 threads (16x16), 2x2 micro-tile. ~4x faster wall time per CTA than 64x64.
// ---------------------------------------------------------------------------
template <int TRANS_B>
__global__ __launch_bounds__(256) void gemm32(const float* __restrict__ A,
                                              const float* __restrict__ Bm,
                                              float* __restrict__ C,
                                              int M, int Nn, int Kk, float scale) {
    __shared__ float As[32][33];
    __shared__ float Bs[32][33];
    const int tid = threadIdx.x;
    const int tx = tid & 15, ty = tid >> 4;
    const int m0 = blockIdx.y * 32, n0 = blockIdx.x * 32;
    float c00 = 0.f, c01 = 0.f, c10 = 0.f, c11 = 0.f;

    for (int k0 = 0; k0 < Kk; k0 += 32) {
        #pragma unroll
        for (int j = 0; j < 4; j++) {
            int e = tid * 4 + j;
            int m = e >> 5, k = e & 31;
            As[k][m] = A[(size_t)(m0 + m) * Kk + k0 + k];
        }
        #pragma unroll
        for (int j = 0; j < 4; j++) {
            int e = tid * 4 + j;
            if (TRANS_B) {
                int n = e >> 5, k = e & 31;
                Bs[k][n] = Bm[(size_t)(n0 + n) * Kk + k0 + k];
            } else {
                int k = e >> 5, n = e & 31;
                Bs[k][n] = Bm[(size_t)(k0 + k) * Nn + n0 + n];
            }
        }
        __syncthreads();
        #pragma unroll
        for (int k = 0; k < 32; k++) {
            float a0 = As[k][ty * 2], a1 = As[k][ty * 2 + 1];
            float b0 = Bs[k][tx * 2], b1 = Bs[k][tx * 2 + 1];
            c00 += a0 * b0; c01 += a0 * b1;
            c10 += a1 * b0; c11 += a1 * b1;
        }
        __syncthreads();
    }
    float* Cp = C + (size_t)(m0 + ty * 2) * Nn + n0 + tx * 2;
    Cp[0] = c00 * scale;  Cp[1] = c01 * scale;
    Cp[Nn] = c10 * scale; Cp[Nn + 1] = c11 * scale;
}

// ---------------------------------------------------------------------------
// Fused per-batch kernel: one CTA per batch b, 512 threads, 2 CTAs/SM.
//   Pass A (w descending): t[f] = sum_w w[w]*x[b,w,f]        -> smem ts
//   Matvec:                qk[f'] = sum_f ts[f]*Mqk[f,f']     (Mqk L2-resident)
//   Pass B (w ascending):  scores + online softmax + y        (cp.async pipeline)
// Dynamic smem: ts[512] | qks[512] (ws during pass A) | buf0[WT*512] | buf1[WT*512]
// ---------------------------------------------------------------------------
__global__ __launch_bounds__(512, 2) void k_fused(const float* __restrict__ x,
                                                  const float* __restrict__ wvec,
                                                  const float* __restrict__ Mqk) {
    extern __shared__ float sm[];
    float* ts   = sm;                 // 512
    float* qks  = sm + F_;            // 512 (holds wvec during pass A)
    float* buf0 = sm + 2 * F_;        // WT*512
    float* buf1 = buf0 + WT * F_;     // WT*512
    __shared__ float sc[WT];

    const int b = blockIdx.x, tid = threadIdx.x;
    const int wi = tid >> 5, lane = tid & 31;
    const float* xb = x + (size_t)b * W_ * F_;

    // ---- stage word-weight vector ----
    qks[tid] = wvec[tid];
    __syncthreads();

    // ---- Pass A: t (reverse order so pass B's start is L2-warm) ----
    {
        float a0 = 0.f, a1 = 0.f, a2 = 0.f, a3 = 0.f;
        #pragma unroll 2
        for (int i = 0; i < W_; i += 4) {
            const int w = W_ - 4 - i;
            a0 += qks[w + 3] * xb[(size_t)(w + 3) * F_ + tid];
            a1 += qks[w + 2] * xb[(size_t)(w + 2) * F_ + tid];
            a2 += qks[w + 1] * xb[(size_t)(w + 1) * F_ + tid];
            a3 += qks[w + 0] * xb[(size_t)(w + 0) * F_ + tid];
        }
        ts[tid] = (a0 + a1) + (a2 + a3);
    }
    __syncthreads();   // ts visible; all reads of qks(=ws) complete

    // ---- Matvec: qk[tid] = sum_f ts[f] * Mqk[f*F_ + tid] ----
    {
        float q0 = 0.f, q1 = 0.f, q2 = 0.f, q3 = 0.f;
        const float* Mp = Mqk + tid;
        #pragma unroll 2
        for (int f = 0; f < F_; f += 4) {
            q0 += ts[f + 0] * Mp[(size_t)(f + 0) * F_];
            q1 += ts[f + 1] * Mp[(size_t)(f + 1) * F_];
            q2 += ts[f + 2] * Mp[(size_t)(f + 2) * F_];
            q3 += ts[f + 3] * Mp[(size_t)(f + 3) * F_];
        }
        qks[tid] = (q0 + q1) + (q2 + q3);   // own slot; others only read ts here
    }

    // ---- Preload tile 0 for pass B ----
    const float4* xb4 = (const float4*)xb;
    #pragma unroll
    for (int j = 0; j < 4; j++) {
        int e = tid + j * 512;               // 0..2047
        int w = e >> 7, f4 = e & 127;
        cp_async16(&buf0[w * F_ + f4 * 4], &xb4[(size_t)w * 128 + f4]);
    }
    cp_commit();
    __syncthreads();                         // qks complete + visible

    float qkr[16];
    #pragma unroll
    for (int j = 0; j < 16; j++) qkr[j] = qks[lane + 32 * j];

    float* bufs[2] = { buf0, buf1 };
    float m = -1e30f, s = 0.f, y = 0.f;

    // ---- Pass B: scores + online softmax + weighted accumulate ----
    for (int t = 0; t < W_ / WT; t++) {
        const int cur = t & 1, nxt = cur ^ 1;
        if (t < W_ / WT - 1) {
            const int t0 = (t + 1) * WT;
            #pragma unroll
            for (int j = 0; j < 4; j++) {
                int e = tid + j * 512;
                int w = e >> 7, f4 = e & 127;
                cp_async16(&bufs[nxt][w * F_ + f4 * 4], &xb4[(size_t)(t0 + w) * 128 + f4]);
            }
            cp_commit();
            cp_wait<1>();
        } else {
            cp_wait<0>();
        }
        __syncthreads();

        // Each warp: one word's dot product (Mqk already carries rsqrt(N))
        float d = 0.f;
        const float* xw = &bufs[cur][wi * F_];
        #pragma unroll
        for (int j = 0; j < 16; j++) d += xw[lane + 32 * j] * qkr[j];
        #pragma unroll
        for (int o = 16; o > 0; o >>= 1) d += __shfl_xor_sync(0xffffffffu, d, o);
        if (lane == 0) sc[wi] = d;
        __syncthreads();

        // Online softmax update (thread owns f = tid)
        float mn = m;
        #pragma unroll
        for (int w = 0; w < WT; w++) mn = fmaxf(mn, sc[w]);
        const float corr = __expf(m - mn);
        s *= corr;
        y *= corr;
        #pragma unroll
        for (int w = 0; w < WT; w++) {
            float p = __expf(sc[w] - mn);
            s += p;
            y += p * bufs[cur][w * F_ + tid];
        }
        m = mn;
        __syncthreads();
    }
    g_y[b * F_ + tid] = y / s;
}

// ---------------------------------------------------------------------------
extern "C" void kernel_launch(void* const* d_in, const int* in_sizes, int n_in,
                              void* d_out, int out_size) {
    const float* x    = (const float*)d_in[0];
    const float* wk   = (const float*)d_in[1];
    const float* wq   = (const float*)d_in[2];
    const float* wv   = (const float*)d_in[3];
    const float* wvec = (const float*)d_in[4];
    float* out = (float*)d_out;

    float *pM, *py;
    cudaGetSymbolAddress((void**)&pM, g_Mqk);
    cudaGetSymbolAddress((void**)&py, g_y);

    const int fused_smem = (2 * F_ + 2 * WT * F_) * sizeof(float);   // 69632
    cudaFuncSetAttribute(k_fused, cudaFuncAttributeMaxDynamicSharedMemorySize, fused_smem);

    const float rsqrtN = 0.04419417382415922f;  // 1/sqrt(512)

    // K0: Mqk = (wq @ wk^T) * rsqrt(N)   — weights only
    gemm32<1><<<dim3(F_ / 32, F_ / 32), 256>>>(wq, wk, pM, F_, F_, N_, rsqrtN);
    // K1: fused t -> qk -> attention -> y   (both passes over x)
    k_fused<<<B_, 512, fused_smem>>>(x, wvec, pM);
    // K2: out = y @ wv
    gemm32<0><<<dim3(N_ / 32, B_ / 32), 256>>>(py, wv, out, B_, N_, F_, 1.f);
}

// round 6
// speedup vs baseline: 1.5343x; 1.0455x over previous
#include <cuda_runtime.h>
#include <math.h>
#include <stddef.h>
#include <stdint.h>

#define B_ 256
#define W_ 512
#define F_ 512
#define N_ 512
#define WT 16   // words per tile in pass B (== #warps)

// Scratch (device globals — no allocation allowed)
__device__ float g_t [B_*F_];   // t  = sum_w w[w]*x[b,w,:]
__device__ float g_q [B_*N_];   // Q  = t @ wq
__device__ float g_qk[B_*F_];   // qk = (Q @ wk^T) * rsqrt(N)
__device__ float g_y [B_*F_];   // y  = sum_w softmax_w * x[b,w,:]

// ---------------------------------------------------------------------------
// cp.async helpers
// ---------------------------------------------------------------------------
__device__ __forceinline__ void cp_async16(void* dst_smem, const void* src_gmem) {
    uint32_t d = (uint32_t)__cvta_generic_to_shared(dst_smem);
    asm volatile("cp.async.cg.shared.global [%0], [%1], 16;\n" :: "r"(d), "l"(src_gmem));
}
__device__ __forceinline__ void cp_commit() {
    asm volatile("cp.async.commit_group;\n");
}
template <int Nw>
__device__ __forceinline__ void cp_wait() {
    asm volatile("cp.async.wait_group %0;\n" :: "n"(Nw));
}

// ---------------------------------------------------------------------------
// Pass A: t[b][f] = sum_w w[w] * x[b][w][f].  2 batches/CTA, grid 128 = 1 wave.
// w processed DESCENDING so low-w x lines are L2-resident when pass B starts.
// ---------------------------------------------------------------------------
__global__ __launch_bounds__(512) void k_t(const float* __restrict__ x,
                                           const float* __restrict__ wvec) {
    __shared__ float ws[W_];
    __shared__ float4 red[2][4][128];   // 16 KB
    const int tid = threadIdx.x;
    const int q = tid >> 7, c4 = tid & 127;
    ws[tid] = wvec[tid];
    __syncthreads();

    const int b0 = blockIdx.x * 2;
    const float4* x0 = (const float4*)(x + (size_t)b0 * W_ * F_) + c4;
    const float4* x1 = (const float4*)(x + (size_t)(b0 + 1) * W_ * F_) + c4;

    float4 a0 = {0.f, 0.f, 0.f, 0.f};
    float4 a1 = {0.f, 0.f, 0.f, 0.f};
    const int wbase = q * 128;
    #pragma unroll 4
    for (int i = 127; i >= 0; i--) {     // descending within quarter
        const int w = wbase + i;
        const float wv = ws[w];
        const float4 v0 = x0[(size_t)w * 128];
        const float4 v1 = x1[(size_t)w * 128];
        a0.x += wv * v0.x; a0.y += wv * v0.y; a0.z += wv * v0.z; a0.w += wv * v0.w;
        a1.x += wv * v1.x; a1.y += wv * v1.y; a1.z += wv * v1.z; a1.w += wv * v1.w;
    }
    red[0][q][c4] = a0;
    red[1][q][c4] = a1;
    __syncthreads();

    if (tid < 256) {
        const int bs = tid >> 7, c = tid & 127;
        float4 r0 = red[bs][0][c], r1 = red[bs][1][c];
        float4 r2 = red[bs][2][c], r3 = red[bs][3][c];
        float4 o;
        o.x = (r0.x + r1.x) + (r2.x + r3.x);
        o.y = (r0.y + r1.y) + (r2.y + r3.y);
        o.z = (r0.z + r1.z) + (r2.z + r3.z);
        o.w = (r0.w + r1.w) + (r2.w + r3.w);
        ((float4*)(g_t + (size_t)(b0 + bs) * F_))[c] = o;
    }
}

// ---------------------------------------------------------------------------
// 32x32 tiled SGEMM, BK=32, 256 threads, 2x2 micro with vectorized LDS.64.
// C = A[M,Kk] @ (TRANS_B ? Bm[Nn,Kk]^T : Bm[Kk,Nn]) * scale
// Smem rows padded to 36 floats (144 B): 8B/16B aligned rows -> LDS.64 legal.
// ---------------------------------------------------------------------------
template <int TRANS_B>
__global__ __launch_bounds__(256) void gemm32(const float* __restrict__ A,
                                              const float* __restrict__ Bm,
                                              float* __restrict__ C,
                                              int M, int Nn, int Kk, float scale) {
    __shared__ float As[32][36];
    __shared__ float Bs[32][36];
    const int tid = threadIdx.x;
    const int tx = tid & 15, ty = tid >> 4;
    const int m0 = blockIdx.y * 32, n0 = blockIdx.x * 32;
    float c00 = 0.f, c01 = 0.f, c10 = 0.f, c11 = 0.f;

    // load indices: float4 along the contiguous (K or N) axis
    const int lm = tid >> 3, lk4 = tid & 7;       // A: row m=lm, k-chunk lk4

    for (int k0 = 0; k0 < Kk; k0 += 32) {
        {   // A tile 32x32: A[m0+lm][k0 + lk4*4 ..]
            float4 v = *(const float4*)&A[(size_t)(m0 + lm) * Kk + k0 + lk4 * 4];
            As[lk4 * 4 + 0][lm] = v.x;
            As[lk4 * 4 + 1][lm] = v.y;
            As[lk4 * 4 + 2][lm] = v.z;
            As[lk4 * 4 + 3][lm] = v.w;
        }
        if (TRANS_B) {   // Bm[Nn,Kk]: row n=lm, k-chunk lk4 -> Bs[k][n]
            float4 v = *(const float4*)&Bm[(size_t)(n0 + lm) * Kk + k0 + lk4 * 4];
            Bs[lk4 * 4 + 0][lm] = v.x;
            Bs[lk4 * 4 + 1][lm] = v.y;
            Bs[lk4 * 4 + 2][lm] = v.z;
            Bs[lk4 * 4 + 3][lm] = v.w;
        } else {         // Bm[Kk,Nn]: row k=lm, n-chunk lk4 -> Bs[k][n..]
            float4 v = *(const float4*)&Bm[(size_t)(k0 + lm) * Nn + n0 + lk4 * 4];
            Bs[lm][lk4 * 4 + 0] = v.x;
            Bs[lm][lk4 * 4 + 1] = v.y;
            Bs[lm][lk4 * 4 + 2] = v.z;
            Bs[lm][lk4 * 4 + 3] = v.w;
        }
        __syncthreads();
        #pragma unroll
        for (int k = 0; k < 32; k++) {
            const float2 a = *(const float2*)&As[k][ty * 2];
            const float2 b = *(const float2*)&Bs[k][tx * 2];
            c00 += a.x * b.x; c01 += a.x * b.y;
            c10 += a.y * b.x; c11 += a.y * b.y;
        }
        __syncthreads();
    }
    float* Cp = C + (size_t)(m0 + ty * 2) * Nn + n0 + tx * 2;
    Cp[0] = c00 * scale;  Cp[1] = c01 * scale;
    Cp[Nn] = c10 * scale; Cp[Nn + 1] = c11 * scale;
}

// ---------------------------------------------------------------------------
// Pass B: scores + online softmax + weighted accumulate. One CTA per batch,
// 512 threads, 2 CTAs/SM, cp.async double buffer.
// Softmax weights p[w] computed ONCE by 16 threads (not 512x redundantly).
// Dynamic smem: qks[512] | buf0[WT*512] | buf1[WT*512]
// ---------------------------------------------------------------------------
__global__ __launch_bounds__(512, 2) void k_attn(const float* __restrict__ x) {
    extern __shared__ float sm[];
    float* qks  = sm;                  // 512
    float* buf0 = sm + F_;             // WT*512
    float* buf1 = buf0 + WT * F_;      // WT*512
    __shared__ float sc[WT];
    __shared__ float ps[WT];

    const int b = blockIdx.x, tid = threadIdx.x;
    const int wi = tid >> 5, lane = tid & 31;

    qks[tid] = g_qk[b * F_ + tid];
    const float4* xb4 = (const float4*)(x + (size_t)b * W_ * F_);

    // Preload tile 0
    #pragma unroll
    for (int j = 0; j < 4; j++) {
        int e = tid + j * 512;               // 0..2047
        int w = e >> 7, f4 = e & 127;
        cp_async16(&buf0[w * F_ + f4 * 4], &xb4[(size_t)w * 128 + f4]);
    }
    cp_commit();
    __syncthreads();                         // qks visible

    float qkr[16];
    #pragma unroll
    for (int j = 0; j < 16; j++) qkr[j] = qks[lane + 32 * j];

    float* bufs[2] = { buf0, buf1 };
    float m = -1e30f, s = 0.f, y = 0.f;

    for (int t = 0; t < W_ / WT; t++) {
        const int cur = t & 1, nxt = cur ^ 1;
        if (t < W_ / WT - 1) {
            const int t0 = (t + 1) * WT;
            #pragma unroll
            for (int j = 0; j < 4; j++) {
                int e = tid + j * 512;
                int w = e >> 7, f4 = e & 127;
                cp_async16(&bufs[nxt][w * F_ + f4 * 4], &xb4[(size_t)(t0 + w) * 128 + f4]);
            }
            cp_commit();
            cp_wait<1>();
        } else {
            cp_wait<0>();
        }
        __syncthreads();                     // tile cur ready (also guards sc reuse)

        // Each warp: one word's dot product (qk already carries rsqrt(N))
        float d = 0.f;
        const float* xw = &bufs[cur][wi * F_];
        #pragma unroll
        for (int j = 0; j < 16; j++) d += xw[lane + 32 * j] * qkr[j];
        #pragma unroll
        for (int o = 16; o > 0; o >>= 1) d += __shfl_xor_sync(0xffffffffu, d, o);
        if (lane == 0) sc[wi] = d;
        __syncthreads();                     // sc ready

        // mn/corr are uniform across threads (cheap); p[w] computed once
        float mn = m;
        #pragma unroll
        for (int w = 0; w < WT; w++) mn = fmaxf(mn, sc[w]);
        const float corr = __expf(m - mn);
        if (tid < WT) ps[tid] = __expf(sc[tid] - mn);
        m = mn;
        __syncthreads();                     // ps ready

        // Accumulate (thread owns f = tid)
        float pr[WT];
        #pragma unroll
        for (int w = 0; w < WT; w++) pr[w] = ps[w];
        float psum = 0.f;
        #pragma unroll
        for (int w = 0; w < WT; w++) psum += pr[w];
        s = s * corr + psum;
        y *= corr;
        #pragma unroll
        for (int w = 0; w < WT; w++) y += pr[w] * bufs[cur][w * F_ + tid];
        // no tail barrier needed: next iter writes bufs[nxt] (disjoint) and
        // sc/ps writes are fenced by the next iteration's barriers.
    }
    g_y[b * F_ + tid] = y / s;
}

// ---------------------------------------------------------------------------
extern "C" void kernel_launch(void* const* d_in, const int* in_sizes, int n_in,
                              void* d_out, int out_size) {
    const float* x    = (const float*)d_in[0];
    const float* wk   = (const float*)d_in[1];
    const float* wq   = (const float*)d_in[2];
    const float* wv   = (const float*)d_in[3];
    const float* wvec = (const float*)d_in[4];
    float* out = (float*)d_out;

    float *pt, *pq, *pqk, *py;
    cudaGetSymbolAddress((void**)&pt,  g_t);
    cudaGetSymbolAddress((void**)&pq,  g_q);
    cudaGetSymbolAddress((void**)&pqk, g_qk);
    cudaGetSymbolAddress((void**)&py,  g_y);

    const int attn_smem = (F_ + 2 * WT * F_) * sizeof(float);   // 67584
    cudaFuncSetAttribute(k_attn, cudaFuncAttributeMaxDynamicSharedMemorySize, attn_smem);

    const float rsqrtN = 0.04419417382415922f;  // 1/sqrt(512)

    // Pass A over x: t
    k_t<<<B_ / 2, 512>>>(x, wvec);
    // Q = t @ wq                 (256x512x512)
    gemm32<0><<<dim3(N_ / 32, B_ / 32), 256>>>(pt, wq, pq, B_, N_, F_, 1.f);
    // qk = (Q @ wk^T) * rsqrtN   (256x512x512)
    gemm32<1><<<dim3(F_ / 32, B_ / 32), 256>>>(pq, wk, pqk, B_, F_, N_, rsqrtN);
    // Pass B over x: attention
    k_attn<<<B_, 512, attn_smem>>>(x);
    // out = y @ wv               (256x512x512)
    gemm32<0><<<dim3(N_ / 32, B_ / 32), 256>>>(py, wv, out, B_, N_, F_, 1.f);
}